// round 5
// baseline (speedup 1.0000x reference)
#include <cuda_runtime.h>

#define MAX_NODES 100000

// Scratch: per-node precomputed partial layer-1 activations.
// P[n] = x[n] @ W1[0:8]          (contribution when n is the "from" endpoint)
// Q[n] = b1 + x[n] @ W1[8:16]    (contribution when n is the "to" endpoint)
__device__ __align__(16) float4 g_P[MAX_NODES * 4];
__device__ __align__(16) float4 g_Q[MAX_NODES * 4];

// Folded weight block (432 floats, 16B-aligned sections):
//   [  0..63 ]  W1e[4][16]   = W1 rows 16..19 (edge_attr part)
//   [ 64..319]  W2g[16][16]  = diag(g1) @ W2
//   [320..335]  cs2[16]      = column sums of W2g
//   [336..351]  b2f[16]      = b2 + be1 @ W2
//   [352..415]  W3g[16][4]   = diag(g2) @ W3
//   [416..419]  cs3[4]       = column sums of W3g
//   [420..423]  b3f[4]       = b3 + be2 @ W3
__device__ __align__(16) float g_fold[432];

__global__ void fold_kernel(const float* __restrict__ W1,
                            const float* __restrict__ g1, const float* __restrict__ be1,
                            const float* __restrict__ W2, const float* __restrict__ b2,
                            const float* __restrict__ g2, const float* __restrict__ be2,
                            const float* __restrict__ W3, const float* __restrict__ b3)
{
    int t = threadIdx.x;  // 256 threads
    if (t < 64) g_fold[t] = W1[256 + t];            // W1 rows 16..19
    g_fold[64 + t] = g1[t >> 4] * W2[t];            // W2g (all 256)
    if (t < 16) {
        float cs = 0.f, bf = b2[t];
        for (int i = 0; i < 16; i++) {
            cs += g1[i] * W2[i * 16 + t];
            bf += be1[i] * W2[i * 16 + t];
        }
        g_fold[320 + t] = cs;
        g_fold[336 + t] = bf;
    }
    if (t < 64) g_fold[352 + t] = g2[t >> 2] * W3[t];   // W3g
    if (t < 4) {
        float cs = 0.f, bf = b3[t];
        for (int i = 0; i < 16; i++) {
            cs += g2[i] * W3[i * 4 + t];
            bf += be2[i] * W3[i * 4 + t];
        }
        g_fold[416 + t] = cs;
        g_fold[420 + t] = bf;
    }
}

__global__ void __launch_bounds__(128) node_kernel(const float4* __restrict__ x4,
                                                   const float* __restrict__ W1,
                                                   const float* __restrict__ b1, int N)
{
    __shared__ float sW[256];   // W1 rows 0..15
    __shared__ float sb[16];
    for (int i = threadIdx.x; i < 256; i += blockDim.x) sW[i] = W1[i];
    if (threadIdx.x < 16) sb[threadIdx.x] = b1[threadIdx.x];
    __syncthreads();

    int n = blockIdx.x * blockDim.x + threadIdx.x;
    if (n >= N) return;

    float4 x0 = x4[n * 2 + 0];
    float4 x1 = x4[n * 2 + 1];
    float xv[8] = {x0.x, x0.y, x0.z, x0.w, x1.x, x1.y, x1.z, x1.w};

    float p[16], q[16];
#pragma unroll
    for (int j = 0; j < 16; j++) { p[j] = 0.f; q[j] = sb[j]; }
#pragma unroll
    for (int i = 0; i < 8; i++) {
        float xi = xv[i];
#pragma unroll
        for (int j = 0; j < 16; j++) {
            p[j] = fmaf(xi, sW[i * 16 + j], p[j]);          // rows 0..7
            q[j] = fmaf(xi, sW[(8 + i) * 16 + j], q[j]);    // rows 8..15
        }
    }
    float4* Pp = &g_P[n * 4];
    float4* Qp = &g_Q[n * 4];
#pragma unroll
    for (int v = 0; v < 4; v++) {
        Pp[v] = make_float4(p[v * 4 + 0], p[v * 4 + 1], p[v * 4 + 2], p[v * 4 + 3]);
        Qp[v] = make_float4(q[v * 4 + 0], q[v * 4 + 1], q[v * 4 + 2], q[v * 4 + 3]);
    }
}

__global__ void __launch_bounds__(256) edge_kernel(const int* __restrict__ ei,
                                                   const float4* __restrict__ ea4,
                                                   float4* __restrict__ out4, int E)
{
    __shared__ __align__(16) float sw[432];
    for (int i = threadIdx.x; i < 432; i += 256) sw[i] = g_fold[i];
    __syncthreads();

    int e = blockIdx.x * 256 + threadIdx.x;
    if (e >= E) return;

    int frm = ei[e];          // edge_index row 0 (int32: JAX x64 is disabled)
    int to  = ei[E + e];      // edge_index row 1

    const float4* Pp = &g_P[frm * 4];
    const float4* Qp = &g_Q[to * 4];

    // u = P[frm] + Q[to] + ea @ W1e   (b1 already folded into Q)
    float a[16];
#pragma unroll
    for (int v = 0; v < 4; v++) {
        float4 p = Pp[v], q = Qp[v];
        a[v * 4 + 0] = p.x + q.x;
        a[v * 4 + 1] = p.y + q.y;
        a[v * 4 + 2] = p.z + q.z;
        a[v * 4 + 3] = p.w + q.w;
    }
    float4 eav = ea4[e];
    float ef[4] = {eav.x, eav.y, eav.z, eav.w};
#pragma unroll
    for (int i = 0; i < 4; i++) {
        float xi = ef[i];
#pragma unroll
        for (int jv = 0; jv < 4; jv++) {
            float4 w = *(const float4*)&sw[i * 16 + jv * 4];
            a[jv * 4 + 0] = fmaf(xi, w.x, a[jv * 4 + 0]);
            a[jv * 4 + 1] = fmaf(xi, w.y, a[jv * 4 + 1]);
            a[jv * 4 + 2] = fmaf(xi, w.z, a[jv * 4 + 2]);
            a[jv * 4 + 3] = fmaf(xi, w.w, a[jv * 4 + 3]);
        }
    }

    // relu + one-pass LN stats
    float sum = 0.f, ss = 0.f;
#pragma unroll
    for (int j = 0; j < 16; j++) {
        float v = fmaxf(a[j], 0.f);
        a[j] = v;
        sum += v;
        ss = fmaf(v, v, ss);
    }
    float mu  = sum * 0.0625f;
    float var = fmaf(ss, 0.0625f, -mu * mu);
    float s1  = rsqrtf(var + 1e-5f);

    // layer 2: t = a @ W2g;  v = s1*t + (b2f - s1*mu*cs2)
    float t[16];
#pragma unroll
    for (int j = 0; j < 16; j++) t[j] = 0.f;
#pragma unroll
    for (int i = 0; i < 16; i++) {
        float ai = a[i];
#pragma unroll
        for (int jv = 0; jv < 4; jv++) {
            float4 w = *(const float4*)&sw[64 + i * 16 + jv * 4];
            t[jv * 4 + 0] = fmaf(ai, w.x, t[jv * 4 + 0]);
            t[jv * 4 + 1] = fmaf(ai, w.y, t[jv * 4 + 1]);
            t[jv * 4 + 2] = fmaf(ai, w.z, t[jv * 4 + 2]);
            t[jv * 4 + 3] = fmaf(ai, w.w, t[jv * 4 + 3]);
        }
    }
    float k1 = s1 * mu;
    float bact[16];
    sum = 0.f; ss = 0.f;
#pragma unroll
    for (int j = 0; j < 16; j++) {
        float c = fmaf(-k1, sw[320 + j], sw[336 + j]);
        float v = fmaf(s1, t[j], c);
        v = fmaxf(v, 0.f);
        bact[j] = v;
        sum += v;
        ss = fmaf(v, v, ss);
    }
    float mu2  = sum * 0.0625f;
    float var2 = fmaf(ss, 0.0625f, -mu2 * mu2);
    float s2   = rsqrtf(var2 + 1e-5f);

    // layer 3: t3 = b @ W3g;  out = s2*t3 + (b3f - s2*mu2*cs3)
    float t3[4] = {0.f, 0.f, 0.f, 0.f};
#pragma unroll
    for (int i = 0; i < 16; i++) {
        float bi = bact[i];
        float4 w = *(const float4*)&sw[352 + i * 4];
        t3[0] = fmaf(bi, w.x, t3[0]);
        t3[1] = fmaf(bi, w.y, t3[1]);
        t3[2] = fmaf(bi, w.z, t3[2]);
        t3[3] = fmaf(bi, w.w, t3[3]);
    }
    float k2 = s2 * mu2;
    float4 o;
    o.x = fmaf(s2, t3[0], fmaf(-k2, sw[416], sw[420]));
    o.y = fmaf(s2, t3[1], fmaf(-k2, sw[417], sw[421]));
    o.z = fmaf(s2, t3[2], fmaf(-k2, sw[418], sw[422]));
    o.w = fmaf(s2, t3[3], fmaf(-k2, sw[419], sw[423]));
    out4[e] = o;
}

extern "C" void kernel_launch(void* const* d_in, const int* in_sizes, int n_in,
                              void* d_out, int out_size)
{
    const float* x   = (const float*)d_in[0];
    const int*   ei  = (const int*)d_in[1];     // int32 (JAX default: x64 disabled)
    const float* ea  = (const float*)d_in[2];
    const float* W1  = (const float*)d_in[3];
    const float* b1  = (const float*)d_in[4];
    const float* g1  = (const float*)d_in[5];
    const float* be1 = (const float*)d_in[6];
    const float* W2  = (const float*)d_in[7];
    const float* b2  = (const float*)d_in[8];
    const float* g2  = (const float*)d_in[9];
    const float* be2 = (const float*)d_in[10];
    const float* W3  = (const float*)d_in[11];
    const float* b3  = (const float*)d_in[12];

    int N = in_sizes[0] / 8;
    if (N > MAX_NODES) N = MAX_NODES;
    int E = in_sizes[1] / 2;

    fold_kernel<<<1, 256>>>(W1, g1, be1, W2, b2, g2, be2, W3, b3);
    node_kernel<<<(N + 127) / 128, 128>>>((const float4*)x, W1, b1, N);
    edge_kernel<<<(E + 255) / 256, 256>>>(ei, (const float4*)ea, (float4*)d_out, E);
}

// round 8
// speedup vs baseline: 1.3684x; 1.3684x over previous
#include <cuda_runtime.h>
#include <cuda_fp16.h>

#define MAX_NODES 100000

typedef unsigned long long u64;

// fp16 per-node precomputed layer-1 partials (32B each = 2 uint4):
// P[n] = x[n] @ W1[0:8]        (from-endpoint part)
// Q[n] = b1 + x[n] @ W1[8:16]  (to-endpoint part)
__device__ __align__(16) uint4 g_Ph[MAX_NODES * 2];
__device__ __align__(16) uint4 g_Qh[MAX_NODES * 2];

// Folded weights (432 floats; all sections 16B-aligned):
//   [  0.. 63]  W1e[4][16]  = W1 rows 16..19
//   [ 64..319]  W2g[16][16] = diag(g1) @ W2
//   [320..335]  cs2[16]     = colsum(W2g)
//   [336..351]  b2f[16]     = b2 + be1 @ W2
//   [352..415]  W3g[16][4]  = diag(g2) @ W3
//   [416..419]  cs3[4]      = colsum(W3g)
//   [420..423]  b3f[4]      = b3 + be2 @ W3
__device__ __align__(16) float g_fold[432];

// ---- packed f32x2 helpers (sm_103a) ----
__device__ __forceinline__ u64 pk(float lo, float hi) {
    u64 r; asm("mov.b64 %0, {%1, %2};" : "=l"(r) : "f"(lo), "f"(hi)); return r;
}
__device__ __forceinline__ float2 upk(u64 v) {
    float2 f; asm("mov.b64 {%0, %1}, %2;" : "=f"(f.x), "=f"(f.y) : "l"(v)); return f;
}
__device__ __forceinline__ u64 fma2(u64 a, u64 b, u64 c) {
    u64 d; asm("fma.rn.f32x2 %0, %1, %2, %3;" : "=l"(d) : "l"(a), "l"(b), "l"(c)); return d;
}
__device__ __forceinline__ u64 add2(u64 a, u64 b) {
    u64 d; asm("add.rn.f32x2 %0, %1, %2;" : "=l"(d) : "l"(a), "l"(b)); return d;
}
// half2 (as uint) -> packed f32x2
__device__ __forceinline__ u64 h2p(unsigned int h) {
    __half2 hh = *(__half2*)&h;
    float2 f = __half22float2(hh);
    return pk(f.x, f.y);
}

__global__ void __launch_bounds__(128)
node_kernel(const float4* __restrict__ x4,
            const float* __restrict__ W1, const float* __restrict__ b1,
            const float* __restrict__ g1, const float* __restrict__ be1,
            const float* __restrict__ W2, const float* __restrict__ b2,
            const float* __restrict__ g2, const float* __restrict__ be2,
            const float* __restrict__ W3, const float* __restrict__ b3,
            int N)
{
    __shared__ float sW[256];
    __shared__ float sb[16];
    for (int i = threadIdx.x; i < 256; i += blockDim.x) sW[i] = W1[i];
    if (threadIdx.x < 16) sb[threadIdx.x] = b1[threadIdx.x];
    __syncthreads();

    // Block 0 additionally computes the folded-weight block (runs once).
    if (blockIdx.x == 0) {
        for (int t = threadIdx.x; t < 256; t += blockDim.x) {
            if (t < 64) g_fold[t] = W1[256 + t];          // W1e
            g_fold[64 + t] = g1[t >> 4] * W2[t];          // W2g
            if (t < 16) {
                float cs = 0.f, bf = b2[t];
                for (int i = 0; i < 16; i++) {
                    cs += g1[i] * W2[i * 16 + t];
                    bf += be1[i] * W2[i * 16 + t];
                }
                g_fold[320 + t] = cs;
                g_fold[336 + t] = bf;
            }
            if (t < 64) g_fold[352 + t] = g2[t >> 2] * W3[t];  // W3g
            if (t < 4) {
                float cs = 0.f, bf = b3[t];
                for (int i = 0; i < 16; i++) {
                    cs += g2[i] * W3[i * 4 + t];
                    bf += be2[i] * W3[i * 4 + t];
                }
                g_fold[416 + t] = cs;
                g_fold[420 + t] = bf;
            }
        }
    }

    int n = blockIdx.x * blockDim.x + threadIdx.x;
    if (n >= N) return;

    float4 x0 = x4[n * 2 + 0];
    float4 x1 = x4[n * 2 + 1];
    float xv[8] = {x0.x, x0.y, x0.z, x0.w, x1.x, x1.y, x1.z, x1.w};

    float p[16], q[16];
#pragma unroll
    for (int j = 0; j < 16; j++) { p[j] = 0.f; q[j] = sb[j]; }
#pragma unroll
    for (int i = 0; i < 8; i++) {
        float xi = xv[i];
#pragma unroll
        for (int j = 0; j < 16; j++) {
            p[j] = fmaf(xi, sW[i * 16 + j], p[j]);
            q[j] = fmaf(xi, sW[(8 + i) * 16 + j], q[j]);
        }
    }
    // Store as fp16 (16 halves = 2 uint4 per table)
    uint4 po[2], qo[2];
#pragma unroll
    for (int v = 0; v < 2; v++) {
        unsigned int* pw = (unsigned int*)&po[v];
        unsigned int* qw = (unsigned int*)&qo[v];
#pragma unroll
        for (int k = 0; k < 4; k++) {
            __half2 hp = __floats2half2_rn(p[v * 8 + k * 2], p[v * 8 + k * 2 + 1]);
            __half2 hq = __floats2half2_rn(q[v * 8 + k * 2], q[v * 8 + k * 2 + 1]);
            pw[k] = *(unsigned int*)&hp;
            qw[k] = *(unsigned int*)&hq;
        }
    }
    g_Ph[n * 2 + 0] = po[0]; g_Ph[n * 2 + 1] = po[1];
    g_Qh[n * 2 + 0] = qo[0]; g_Qh[n * 2 + 1] = qo[1];
}

__global__ void __launch_bounds__(256)
edge_kernel(const int* __restrict__ ei, const float4* __restrict__ ea4,
            float4* __restrict__ out4, int E)
{
    __shared__ __align__(16) float sw[432];
    for (int i = threadIdx.x; i < 432; i += 256) sw[i] = g_fold[i];
    __syncthreads();

    int e = blockIdx.x * 256 + threadIdx.x;
    if (e >= E) return;

    int frm = ei[e];
    int to  = ei[E + e];

    // ---- gather fp16 P[frm], Q[to] (2 x 32B each), convert, add ----
    uint4 p0 = g_Ph[frm * 2], p1 = g_Ph[frm * 2 + 1];
    uint4 q0 = g_Qh[to * 2],  q1 = g_Qh[to * 2 + 1];

    u64 a2[8];
    a2[0] = add2(h2p(p0.x), h2p(q0.x));
    a2[1] = add2(h2p(p0.y), h2p(q0.y));
    a2[2] = add2(h2p(p0.z), h2p(q0.z));
    a2[3] = add2(h2p(p0.w), h2p(q0.w));
    a2[4] = add2(h2p(p1.x), h2p(q1.x));
    a2[5] = add2(h2p(p1.y), h2p(q1.y));
    a2[6] = add2(h2p(p1.z), h2p(q1.z));
    a2[7] = add2(h2p(p1.w), h2p(q1.w));

    // ---- + ea @ W1e ----
    float4 eav = ea4[e];
    float ef[4] = {eav.x, eav.y, eav.z, eav.w};
#pragma unroll
    for (int i = 0; i < 4; i++) {
        u64 ei2 = pk(ef[i], ef[i]);
        const ulonglong2* wr = (const ulonglong2*)&sw[i * 16];
#pragma unroll
        for (int k = 0; k < 4; k++) {
            ulonglong2 w = wr[k];
            a2[k * 2 + 0] = fma2(ei2, w.x, a2[k * 2 + 0]);
            a2[k * 2 + 1] = fma2(ei2, w.y, a2[k * 2 + 1]);
        }
    }

    // ---- relu + one-pass LN stats (packed) ----
    float a[16];
    u64 sm2 = 0ull, ss2 = 0ull;
#pragma unroll
    for (int k = 0; k < 8; k++) {
        float2 f = upk(a2[k]);
        f.x = fmaxf(f.x, 0.f); f.y = fmaxf(f.y, 0.f);
        a[2 * k] = f.x; a[2 * k + 1] = f.y;
        u64 v = pk(f.x, f.y);
        sm2 = add2(sm2, v);
        ss2 = fma2(v, v, ss2);
    }
    float2 sh = upk(sm2), qh = upk(ss2);
    float mu  = (sh.x + sh.y) * 0.0625f;
    float var = fmaf(qh.x + qh.y, 0.0625f, -mu * mu);
    float s1  = rsqrtf(var + 1e-5f);

    // ---- layer 2 GEMV (packed): t = a @ W2g ----
    u64 t2[8];
#pragma unroll
    for (int k = 0; k < 8; k++) t2[k] = 0ull;
#pragma unroll
    for (int i = 0; i < 16; i++) {
        u64 ai2 = pk(a[i], a[i]);
        const ulonglong2* wr = (const ulonglong2*)&sw[64 + i * 16];
#pragma unroll
        for (int k = 0; k < 4; k++) {
            ulonglong2 w = wr[k];
            t2[k * 2 + 0] = fma2(ai2, w.x, t2[k * 2 + 0]);
            t2[k * 2 + 1] = fma2(ai2, w.y, t2[k * 2 + 1]);
        }
    }

    // ---- epilogue 2: v = s1*t + (b2f - s1*mu*cs2), relu, stats ----
    float k1 = s1 * mu;
    u64 nk1 = pk(-k1, -k1), s1p = pk(s1, s1);
    const u64* cs2p = (const u64*)&sw[320];
    const u64* b2fp = (const u64*)&sw[336];
    float b[16];
    sm2 = 0ull; ss2 = 0ull;
#pragma unroll
    for (int k = 0; k < 8; k++) {
        u64 c = fma2(nk1, cs2p[k], b2fp[k]);
        u64 v = fma2(s1p, t2[k], c);
        float2 f = upk(v);
        f.x = fmaxf(f.x, 0.f); f.y = fmaxf(f.y, 0.f);
        b[2 * k] = f.x; b[2 * k + 1] = f.y;
        u64 vv = pk(f.x, f.y);
        sm2 = add2(sm2, vv);
        ss2 = fma2(vv, vv, ss2);
    }
    sh = upk(sm2); qh = upk(ss2);
    float mu2  = (sh.x + sh.y) * 0.0625f;
    float var2 = fmaf(qh.x + qh.y, 0.0625f, -mu2 * mu2);
    float s2   = rsqrtf(var2 + 1e-5f);

    // ---- layer 3 (packed): t3 = b @ W3g ----
    u64 t3a = 0ull, t3b = 0ull;
#pragma unroll
    for (int i = 0; i < 16; i++) {
        u64 bi2 = pk(b[i], b[i]);
        ulonglong2 w = *(const ulonglong2*)&sw[352 + i * 4];
        t3a = fma2(bi2, w.x, t3a);
        t3b = fma2(bi2, w.y, t3b);
    }
    float k2 = s2 * mu2;
    u64 nk2 = pk(-k2, -k2), s2p = pk(s2, s2);
    u64 oa = fma2(s2p, t3a, fma2(nk2, *(const u64*)&sw[416], *(const u64*)&sw[420]));
    u64 ob = fma2(s2p, t3b, fma2(nk2, *(const u64*)&sw[418], *(const u64*)&sw[422]));
    float2 fa = upk(oa), fb = upk(ob);
    out4[e] = make_float4(fa.x, fa.y, fb.x, fb.y);
}

extern "C" void kernel_launch(void* const* d_in, const int* in_sizes, int n_in,
                              void* d_out, int out_size)
{
    const float* x   = (const float*)d_in[0];
    const int*   ei  = (const int*)d_in[1];     // int32 (JAX x64 disabled)
    const float* ea  = (const float*)d_in[2];
    const float* W1  = (const float*)d_in[3];
    const float* b1  = (const float*)d_in[4];
    const float* g1  = (const float*)d_in[5];
    const float* be1 = (const float*)d_in[6];
    const float* W2  = (const float*)d_in[7];
    const float* b2  = (const float*)d_in[8];
    const float* g2  = (const float*)d_in[9];
    const float* be2 = (const float*)d_in[10];
    const float* W3  = (const float*)d_in[11];
    const float* b3  = (const float*)d_in[12];

    int N = in_sizes[0] / 8;
    if (N > MAX_NODES) N = MAX_NODES;
    int E = in_sizes[1] / 2;

    node_kernel<<<(N + 127) / 128, 128>>>((const float4*)x, W1, b1,
                                          g1, be1, W2, b2, g2, be2, W3, b3, N);
    edge_kernel<<<(E + 255) / 256, 256>>>(ei, (const float4*)ea, (float4*)d_out, E);
}

// round 9
// speedup vs baseline: 1.5432x; 1.1277x over previous
#include <cuda_runtime.h>
#include <cuda_fp16.h>

#define MAX_NODES 100000

typedef unsigned long long u64;

// fp16 node features: x[n] as 8 halves = 16B -> ONE gather per endpoint.
__device__ __align__(16) uint4 g_xh[MAX_NODES];

// Folded weights (696 floats, all sections 16B aligned):
//   [  0.. 15]  b1[16]
//   [ 16..335]  W1[20][16]   (rows 0..7 frm, 8..15 to, 16..19 edge_attr)
//   [336..591]  W2g[16][16] = diag(g1) @ W2
//   [592..607]  cs2[16]     = colsum(W2g)
//   [608..623]  b2f[16]     = b2 + be1 @ W2
//   [624..687]  W3g[16][4]  = diag(g2) @ W3
//   [688..691]  cs3[4]      = colsum(W3g)
//   [692..695]  b3f[4]      = b3 + be2 @ W3
__device__ __align__(16) float g_fold[696];

// ---- packed f32x2 helpers (sm_103a) ----
__device__ __forceinline__ u64 pk(float lo, float hi) {
    u64 r; asm("mov.b64 %0, {%1, %2};" : "=l"(r) : "f"(lo), "f"(hi)); return r;
}
__device__ __forceinline__ u64 pk1(float v) { return pk(v, v); }
__device__ __forceinline__ float2 upk(u64 v) {
    float2 f; asm("mov.b64 {%0, %1}, %2;" : "=f"(f.x), "=f"(f.y) : "l"(v)); return f;
}
__device__ __forceinline__ u64 fma2(u64 a, u64 b, u64 c) {
    u64 d; asm("fma.rn.f32x2 %0, %1, %2, %3;" : "=l"(d) : "l"(a), "l"(b), "l"(c)); return d;
}
__device__ __forceinline__ u64 add2(u64 a, u64 b) {
    u64 d; asm("add.rn.f32x2 %0, %1, %2;" : "=l"(d) : "l"(a), "l"(b)); return d;
}
// uint4 of 8 halves -> 8 floats
__device__ __forceinline__ void h8f(uint4 h, float* f) {
    float2 t;
    t = __half22float2(*(__half2*)&h.x); f[0] = t.x; f[1] = t.y;
    t = __half22float2(*(__half2*)&h.y); f[2] = t.x; f[3] = t.y;
    t = __half22float2(*(__half2*)&h.z); f[4] = t.x; f[5] = t.y;
    t = __half22float2(*(__half2*)&h.w); f[6] = t.x; f[7] = t.y;
}

// relu + one-pass LN stats on 8 packed accumulators -> 16 floats + (s, s*mu)
__device__ __forceinline__ void relu_stats(const u64* acc, float* af, float& s, float& k) {
    u64 sm = 0ull, ss = 0ull;
#pragma unroll
    for (int i = 0; i < 8; i++) {
        float2 f = upk(acc[i]);
        f.x = fmaxf(f.x, 0.f); f.y = fmaxf(f.y, 0.f);
        af[2 * i] = f.x; af[2 * i + 1] = f.y;
        u64 v = pk(f.x, f.y);
        sm = add2(sm, v);
        ss = fma2(v, v, ss);
    }
    float2 sh = upk(sm), qh = upk(ss);
    float mu  = (sh.x + sh.y) * 0.0625f;
    float var = fmaf(qh.x + qh.y, 0.0625f, -mu * mu);
    s = rsqrtf(var + 1e-5f);
    k = s * mu;
}

// epilogue 2: v = s1*t + (b2f - k1*cs2), relu, stats
__device__ __forceinline__ void epi2(const float* sw, const u64* t2,
                                     float s1, float k1,
                                     float* bf, float& s2, float& k2) {
    u64 nk1 = pk1(-k1), s1p = pk1(s1);
    const u64* csp = (const u64*)&sw[592];
    const u64* bfp = (const u64*)&sw[608];
    u64 sm = 0ull, ss = 0ull;
#pragma unroll
    for (int i = 0; i < 8; i++) {
        u64 c = fma2(nk1, csp[i], bfp[i]);
        u64 v = fma2(s1p, t2[i], c);
        float2 f = upk(v);
        f.x = fmaxf(f.x, 0.f); f.y = fmaxf(f.y, 0.f);
        bf[2 * i] = f.x; bf[2 * i + 1] = f.y;
        u64 vv = pk(f.x, f.y);
        sm = add2(sm, vv);
        ss = fma2(vv, vv, ss);
    }
    float2 sh = upk(sm), qh = upk(ss);
    float mu  = (sh.x + sh.y) * 0.0625f;
    float var = fmaf(qh.x + qh.y, 0.0625f, -mu * mu);
    s2 = rsqrtf(var + 1e-5f);
    k2 = s2 * mu;
}

__global__ void __launch_bounds__(128)
node_kernel(const float4* __restrict__ x4,
            const float* __restrict__ W1, const float* __restrict__ b1,
            const float* __restrict__ g1, const float* __restrict__ be1,
            const float* __restrict__ W2, const float* __restrict__ b2,
            const float* __restrict__ g2, const float* __restrict__ be2,
            const float* __restrict__ W3, const float* __restrict__ b3,
            int N)
{
    // Block 0 computes the folded-weight block (runs once per launch).
    if (blockIdx.x == 0) {
        for (int t = threadIdx.x; t < 320; t += blockDim.x) {
            if (t < 16) g_fold[t] = b1[t];
            g_fold[16 + t] = W1[t];                    // full W1 (320)
            if (t < 256) g_fold[336 + t] = g1[t >> 4] * W2[t];
            if (t < 16) {
                float cs = 0.f, bf = b2[t];
                for (int i = 0; i < 16; i++) {
                    cs += g1[i] * W2[i * 16 + t];
                    bf += be1[i] * W2[i * 16 + t];
                }
                g_fold[592 + t] = cs;
                g_fold[608 + t] = bf;
            }
            if (t < 64) g_fold[624 + t] = g2[t >> 2] * W3[t];
            if (t < 4) {
                float cs = 0.f, bf = b3[t];
                for (int i = 0; i < 16; i++) {
                    cs += g2[i] * W3[i * 4 + t];
                    bf += be2[i] * W3[i * 4 + t];
                }
                g_fold[688 + t] = cs;
                g_fold[692 + t] = bf;
            }
        }
    }

    int n = blockIdx.x * blockDim.x + threadIdx.x;
    if (n >= N) return;
    float4 x0 = x4[n * 2 + 0];
    float4 x1 = x4[n * 2 + 1];
    uint4 h;
    __half2 h0 = __floats2half2_rn(x0.x, x0.y);
    __half2 h1 = __floats2half2_rn(x0.z, x0.w);
    __half2 h2 = __floats2half2_rn(x1.x, x1.y);
    __half2 h3 = __floats2half2_rn(x1.z, x1.w);
    h.x = *(unsigned int*)&h0; h.y = *(unsigned int*)&h1;
    h.z = *(unsigned int*)&h2; h.w = *(unsigned int*)&h3;
    g_xh[n] = h;
}

__global__ void __launch_bounds__(256)
edge_kernel(const int* __restrict__ ei, const float4* __restrict__ ea4,
            float4* __restrict__ out4, int E)
{
    __shared__ __align__(16) float sw[696];
    for (int i = threadIdx.x; i < 696; i += 256) sw[i] = g_fold[i];
    __syncthreads();

    int base = blockIdx.x * 512 + threadIdx.x;
    int eA = base, eB = base + 256;
    bool vA = eA < E, vB = eB < E;
    int sA = vA ? eA : 0, sB = vB ? eB : 0;

    // ---- issue all irregular loads up front (max MLP) ----
    int fA = ei[sA],     fB = ei[sB];
    int tA = ei[E + sA], tB = ei[E + sB];
    uint4 hfA = g_xh[fA], htA = g_xh[tA];
    uint4 hfB = g_xh[fB], htB = g_xh[tB];
    float4 eaA = ea4[sA], eaB = ea4[sB];

    float xfA[8], xtA[8], xfB[8], xtB[8];
    h8f(hfA, xfA); h8f(htA, xtA);
    h8f(hfB, xfB); h8f(htB, xtB);

    // ---- layer 1: acc = b1 + xf@W1[0:8] + xt@W1[8:16] + ea@W1[16:20] ----
    u64 aA[8], aB[8];
    {
        const u64* b1p = (const u64*)&sw[0];
#pragma unroll
        for (int k = 0; k < 8; k++) { aA[k] = b1p[k]; aB[k] = aA[k]; }
    }
#pragma unroll
    for (int i = 0; i < 8; i++) {
        const ulonglong2* wr = (const ulonglong2*)&sw[16 + i * 16];
        u64 xA2 = pk1(xfA[i]), xB2 = pk1(xfB[i]);
#pragma unroll
        for (int k = 0; k < 2; k++) {
            ulonglong2 w0 = wr[2 * k], w1 = wr[2 * k + 1];
            aA[4 * k + 0] = fma2(xA2, w0.x, aA[4 * k + 0]);
            aA[4 * k + 1] = fma2(xA2, w0.y, aA[4 * k + 1]);
            aA[4 * k + 2] = fma2(xA2, w1.x, aA[4 * k + 2]);
            aA[4 * k + 3] = fma2(xA2, w1.y, aA[4 * k + 3]);
            aB[4 * k + 0] = fma2(xB2, w0.x, aB[4 * k + 0]);
            aB[4 * k + 1] = fma2(xB2, w0.y, aB[4 * k + 1]);
            aB[4 * k + 2] = fma2(xB2, w1.x, aB[4 * k + 2]);
            aB[4 * k + 3] = fma2(xB2, w1.y, aB[4 * k + 3]);
        }
    }
#pragma unroll
    for (int i = 0; i < 8; i++) {
        const ulonglong2* wr = (const ulonglong2*)&sw[16 + (8 + i) * 16];
        u64 xA2 = pk1(xtA[i]), xB2 = pk1(xtB[i]);
#pragma unroll
        for (int k = 0; k < 2; k++) {
            ulonglong2 w0 = wr[2 * k], w1 = wr[2 * k + 1];
            aA[4 * k + 0] = fma2(xA2, w0.x, aA[4 * k + 0]);
            aA[4 * k + 1] = fma2(xA2, w0.y, aA[4 * k + 1]);
            aA[4 * k + 2] = fma2(xA2, w1.x, aA[4 * k + 2]);
            aA[4 * k + 3] = fma2(xA2, w1.y, aA[4 * k + 3]);
            aB[4 * k + 0] = fma2(xB2, w0.x, aB[4 * k + 0]);
            aB[4 * k + 1] = fma2(xB2, w0.y, aB[4 * k + 1]);
            aB[4 * k + 2] = fma2(xB2, w1.x, aB[4 * k + 2]);
            aB[4 * k + 3] = fma2(xB2, w1.y, aB[4 * k + 3]);
        }
    }
    {
        float efA[4] = {eaA.x, eaA.y, eaA.z, eaA.w};
        float efB[4] = {eaB.x, eaB.y, eaB.z, eaB.w};
#pragma unroll
        for (int i = 0; i < 4; i++) {
            const ulonglong2* wr = (const ulonglong2*)&sw[16 + (16 + i) * 16];
            u64 xA2 = pk1(efA[i]), xB2 = pk1(efB[i]);
#pragma unroll
            for (int k = 0; k < 2; k++) {
                ulonglong2 w0 = wr[2 * k], w1 = wr[2 * k + 1];
                aA[4 * k + 0] = fma2(xA2, w0.x, aA[4 * k + 0]);
                aA[4 * k + 1] = fma2(xA2, w0.y, aA[4 * k + 1]);
                aA[4 * k + 2] = fma2(xA2, w1.x, aA[4 * k + 2]);
                aA[4 * k + 3] = fma2(xA2, w1.y, aA[4 * k + 3]);
                aB[4 * k + 0] = fma2(xB2, w0.x, aB[4 * k + 0]);
                aB[4 * k + 1] = fma2(xB2, w0.y, aB[4 * k + 1]);
                aB[4 * k + 2] = fma2(xB2, w1.x, aB[4 * k + 2]);
                aB[4 * k + 3] = fma2(xB2, w1.y, aB[4 * k + 3]);
            }
        }
    }

    // ---- LN1 stats ----
    float afA[16], afB[16], s1A, k1A, s1B, k1B;
    relu_stats(aA, afA, s1A, k1A);
    relu_stats(aB, afB, s1B, k1B);

    // ---- layer 2 GEMV (weights shared across both edges) ----
    u64 t2A[8], t2B[8];
#pragma unroll
    for (int k = 0; k < 8; k++) { t2A[k] = 0ull; t2B[k] = 0ull; }
#pragma unroll
    for (int i = 0; i < 16; i++) {
        const ulonglong2* wr = (const ulonglong2*)&sw[336 + i * 16];
        u64 xA2 = pk1(afA[i]), xB2 = pk1(afB[i]);
#pragma unroll
        for (int k = 0; k < 2; k++) {
            ulonglong2 w0 = wr[2 * k], w1 = wr[2 * k + 1];
            t2A[4 * k + 0] = fma2(xA2, w0.x, t2A[4 * k + 0]);
            t2A[4 * k + 1] = fma2(xA2, w0.y, t2A[4 * k + 1]);
            t2A[4 * k + 2] = fma2(xA2, w1.x, t2A[4 * k + 2]);
            t2A[4 * k + 3] = fma2(xA2, w1.y, t2A[4 * k + 3]);
            t2B[4 * k + 0] = fma2(xB2, w0.x, t2B[4 * k + 0]);
            t2B[4 * k + 1] = fma2(xB2, w0.y, t2B[4 * k + 1]);
            t2B[4 * k + 2] = fma2(xB2, w1.x, t2B[4 * k + 2]);
            t2B[4 * k + 3] = fma2(xB2, w1.y, t2B[4 * k + 3]);
        }
    }

    // ---- epilogue 2 (per edge) ----
    float bfA[16], bfB[16], s2A, k2A, s2B, k2B;
    epi2(sw, t2A, s1A, k1A, bfA, s2A, k2A);
    epi2(sw, t2B, s1B, k1B, bfB, s2B, k2B);

    // ---- layer 3 (weights shared) ----
    u64 t3aA = 0ull, t3bA = 0ull, t3aB = 0ull, t3bB = 0ull;
#pragma unroll
    for (int i = 0; i < 16; i++) {
        ulonglong2 w = *(const ulonglong2*)&sw[624 + i * 4];
        u64 xA2 = pk1(bfA[i]), xB2 = pk1(bfB[i]);
        t3aA = fma2(xA2, w.x, t3aA);
        t3bA = fma2(xA2, w.y, t3bA);
        t3aB = fma2(xB2, w.x, t3aB);
        t3bB = fma2(xB2, w.y, t3bB);
    }

    u64 cs3a = *(const u64*)&sw[688], cs3b = *(const u64*)&sw[690];
    u64 b3a  = *(const u64*)&sw[692], b3b  = *(const u64*)&sw[694];

    if (vA) {
        u64 nk2 = pk1(-k2A), s2p = pk1(s2A);
        u64 oa = fma2(s2p, t3aA, fma2(nk2, cs3a, b3a));
        u64 ob = fma2(s2p, t3bA, fma2(nk2, cs3b, b3b));
        float2 fa = upk(oa), fb = upk(ob);
        out4[eA] = make_float4(fa.x, fa.y, fb.x, fb.y);
    }
    if (vB) {
        u64 nk2 = pk1(-k2B), s2p = pk1(s2B);
        u64 oa = fma2(s2p, t3aB, fma2(nk2, cs3a, b3a));
        u64 ob = fma2(s2p, t3bB, fma2(nk2, cs3b, b3b));
        float2 fa = upk(oa), fb = upk(ob);
        out4[eB] = make_float4(fa.x, fa.y, fb.x, fb.y);
    }
}

extern "C" void kernel_launch(void* const* d_in, const int* in_sizes, int n_in,
                              void* d_out, int out_size)
{
    const float* x   = (const float*)d_in[0];
    const int*   ei  = (const int*)d_in[1];     // int32 (JAX x64 disabled)
    const float* ea  = (const float*)d_in[2];
    const float* W1  = (const float*)d_in[3];
    const float* b1  = (const float*)d_in[4];
    const float* g1  = (const float*)d_in[5];
    const float* be1 = (const float*)d_in[6];
    const float* W2  = (const float*)d_in[7];
    const float* b2  = (const float*)d_in[8];
    const float* g2  = (const float*)d_in[9];
    const float* be2 = (const float*)d_in[10];
    const float* W3  = (const float*)d_in[11];
    const float* b3  = (const float*)d_in[12];

    int N = in_sizes[0] / 8;
    if (N > MAX_NODES) N = MAX_NODES;
    int E = in_sizes[1] / 2;

    node_kernel<<<(N + 127) / 128, 128>>>((const float4*)x, W1, b1,
                                          g1, be1, W2, b2, g2, be2, W3, b3, N);
    edge_kernel<<<(E + 511) / 512, 256>>>(ei, (const float4*)ea, (float4*)d_out, E);
}

// round 12
// speedup vs baseline: 1.6343x; 1.0591x over previous
#include <cuda_runtime.h>
#include <cuda_fp16.h>

#define MAX_NODES 100000

typedef unsigned long long u64;

// fp16 node features: x[n] as 8 halves = 16B -> ONE gather per endpoint.
__device__ __align__(16) uint4 g_xh[MAX_NODES];

// Folded weights (696 floats, all sections 16B aligned):
//   [  0.. 15]  b1[16]
//   [ 16..335]  W1[20][16]   (rows 0..7 frm, 8..15 to, 16..19 edge_attr)
//   [336..591]  W2g[16][16] = diag(g1) @ W2
//   [592..607]  cs2[16]     = colsum(W2g)
//   [608..623]  b2f[16]     = b2 + be1 @ W2
//   [624..687]  W3g[16][4]  = diag(g2) @ W3
//   [688..691]  cs3[4]      = colsum(W3g)
//   [692..695]  b3f[4]      = b3 + be2 @ W3
__device__ __align__(16) float g_fold[696];

// ---- packed f32x2 helpers (sm_103a) ----
__device__ __forceinline__ u64 pk(float lo, float hi) {
    u64 r; asm("mov.b64 %0, {%1, %2};" : "=l"(r) : "f"(lo), "f"(hi)); return r;
}
__device__ __forceinline__ u64 pk1(float v) { return pk(v, v); }
__device__ __forceinline__ float2 upk(u64 v) {
    float2 f; asm("mov.b64 {%0, %1}, %2;" : "=f"(f.x), "=f"(f.y) : "l"(v)); return f;
}
__device__ __forceinline__ u64 fma2(u64 a, u64 b, u64 c) {
    u64 d; asm("fma.rn.f32x2 %0, %1, %2, %3;" : "=l"(d) : "l"(a), "l"(b), "l"(c)); return d;
}
__device__ __forceinline__ u64 add2(u64 a, u64 b) {
    u64 d; asm("add.rn.f32x2 %0, %1, %2;" : "=l"(d) : "l"(a), "l"(b)); return d;
}
// uint4 of 8 halves -> 8 floats
__device__ __forceinline__ void h8f(uint4 h, float* f) {
    float2 t;
    t = __half22float2(*(__half2*)&h.x); f[0] = t.x; f[1] = t.y;
    t = __half22float2(*(__half2*)&h.y); f[2] = t.x; f[3] = t.y;
    t = __half22float2(*(__half2*)&h.z); f[4] = t.x; f[5] = t.y;
    t = __half22float2(*(__half2*)&h.w); f[6] = t.x; f[7] = t.y;
}

// relu + one-pass LN stats on 8 packed accumulators -> 16 floats + (s, s*mu)
__device__ __forceinline__ void relu_stats(const u64* acc, float* af, float& s, float& k) {
    u64 sm = 0ull, ss = 0ull;
#pragma unroll
    for (int i = 0; i < 8; i++) {
        float2 f = upk(acc[i]);
        f.x = fmaxf(f.x, 0.f); f.y = fmaxf(f.y, 0.f);
        af[2 * i] = f.x; af[2 * i + 1] = f.y;
        u64 v = pk(f.x, f.y);
        sm = add2(sm, v);
        ss = fma2(v, v, ss);
    }
    float2 sh = upk(sm), qh = upk(ss);
    float mu  = (sh.x + sh.y) * 0.0625f;
    float var = fmaf(qh.x + qh.y, 0.0625f, -mu * mu);
    s = rsqrtf(var + 1e-5f);
    k = s * mu;
}

// epilogue 2: v = s1*t + (b2f - k1*cs2), relu, stats
__device__ __forceinline__ void epi2(const float* sw, const u64* t2,
                                     float s1, float k1,
                                     float* bf, float& s2, float& k2) {
    u64 nk1 = pk1(-k1), s1p = pk1(s1);
    const u64* csp = (const u64*)&sw[592];
    const u64* bfp = (const u64*)&sw[608];
    u64 sm = 0ull, ss = 0ull;
#pragma unroll
    for (int i = 0; i < 8; i++) {
        u64 c = fma2(nk1, csp[i], bfp[i]);
        u64 v = fma2(s1p, t2[i], c);
        float2 f = upk(v);
        f.x = fmaxf(f.x, 0.f); f.y = fmaxf(f.y, 0.f);
        bf[2 * i] = f.x; bf[2 * i + 1] = f.y;
        u64 vv = pk(f.x, f.y);
        sm = add2(sm, vv);
        ss = fma2(vv, vv, ss);
    }
    float2 sh = upk(sm), qh = upk(ss);
    float mu  = (sh.x + sh.y) * 0.0625f;
    float var = fmaf(qh.x + qh.y, 0.0625f, -mu * mu);
    s2 = rsqrtf(var + 1e-5f);
    k2 = s2 * mu;
}

__global__ void __launch_bounds__(256)
node_kernel(const float4* __restrict__ x4,
            const float* __restrict__ W1, const float* __restrict__ b1,
            const float* __restrict__ g1, const float* __restrict__ be1,
            const float* __restrict__ W2, const float* __restrict__ b2,
            const float* __restrict__ g2, const float* __restrict__ be2,
            const float* __restrict__ W3, const float* __restrict__ b3,
            int N)
{
    // Block 0 computes the folded-weight block (runs once per launch).
    // NOTE: must be a strided loop — 320 > blockDim.x. (R10/R11 bug: a plain
    // `if (t < 320)` left g_fold[272..335] = W1 rows 16..19 unwritten.)
    if (blockIdx.x == 0) {
        for (int t = threadIdx.x; t < 320; t += blockDim.x) {
            if (t < 16) g_fold[t] = b1[t];
            g_fold[16 + t] = W1[t];                    // full W1 (320)
            if (t < 256) g_fold[336 + t] = g1[t >> 4] * W2[t];
            if (t < 16) {
                float cs = 0.f, bf = b2[t];
                for (int i = 0; i < 16; i++) {
                    cs += g1[i] * W2[i * 16 + t];
                    bf += be1[i] * W2[i * 16 + t];
                }
                g_fold[592 + t] = cs;
                g_fold[608 + t] = bf;
            }
            if (t < 64) g_fold[624 + t] = g2[t >> 2] * W3[t];
            if (t < 4) {
                float cs = 0.f, bf = b3[t];
                for (int i = 0; i < 16; i++) {
                    cs += g2[i] * W3[i * 4 + t];
                    bf += be2[i] * W3[i * 4 + t];
                }
                g_fold[688 + t] = cs;
                g_fold[692 + t] = bf;
            }
        }
    }

    int n = blockIdx.x * blockDim.x + threadIdx.x;
    if (n >= N) return;
    float4 x0 = x4[n * 2 + 0];
    float4 x1 = x4[n * 2 + 1];
    uint4 h;
    __half2 h0 = __floats2half2_rn(x0.x, x0.y);
    __half2 h1 = __floats2half2_rn(x0.z, x0.w);
    __half2 h2 = __floats2half2_rn(x1.x, x1.y);
    __half2 h3 = __floats2half2_rn(x1.z, x1.w);
    h.x = *(unsigned int*)&h0; h.y = *(unsigned int*)&h1;
    h.z = *(unsigned int*)&h2; h.w = *(unsigned int*)&h3;
    g_xh[n] = h;
}

__global__ void __launch_bounds__(128, 6)
edge_kernel(const int* __restrict__ ei, const float4* __restrict__ ea4,
            float4* __restrict__ out4, int E)
{
    __shared__ __align__(16) float sw[696];
    for (int i = threadIdx.x; i < 696; i += 128) sw[i] = g_fold[i];
    __syncthreads();

    int base = blockIdx.x * 256 + threadIdx.x;
    int eA = base, eB = base + 128;
    bool vA = eA < E, vB = eB < E;
    int sA = vA ? eA : 0, sB = vB ? eB : 0;

    // ---- issue all irregular loads up front (max MLP) ----
    int fA = ei[sA],     fB = ei[sB];
    int tA = ei[E + sA], tB = ei[E + sB];
    uint4 hfA = g_xh[fA], htA = g_xh[tA];
    uint4 hfB = g_xh[fB], htB = g_xh[tB];
    float4 eaA = ea4[sA], eaB = ea4[sB];

    float xfA[8], xtA[8], xfB[8], xtB[8];
    h8f(hfA, xfA); h8f(htA, xtA);
    h8f(hfB, xfB); h8f(htB, xtB);

    // ---- layer 1: acc = b1 + xf@W1[0:8] + xt@W1[8:16] + ea@W1[16:20] ----
    u64 aA[8], aB[8];
    {
        const u64* b1p = (const u64*)&sw[0];
#pragma unroll
        for (int k = 0; k < 8; k++) { aA[k] = b1p[k]; aB[k] = aA[k]; }
    }
#pragma unroll
    for (int i = 0; i < 8; i++) {
        const ulonglong2* wr = (const ulonglong2*)&sw[16 + i * 16];
        u64 xA2 = pk1(xfA[i]), xB2 = pk1(xfB[i]);
#pragma unroll
        for (int k = 0; k < 2; k++) {
            ulonglong2 w0 = wr[2 * k], w1 = wr[2 * k + 1];
            aA[4 * k + 0] = fma2(xA2, w0.x, aA[4 * k + 0]);
            aA[4 * k + 1] = fma2(xA2, w0.y, aA[4 * k + 1]);
            aA[4 * k + 2] = fma2(xA2, w1.x, aA[4 * k + 2]);
            aA[4 * k + 3] = fma2(xA2, w1.y, aA[4 * k + 3]);
            aB[4 * k + 0] = fma2(xB2, w0.x, aB[4 * k + 0]);
            aB[4 * k + 1] = fma2(xB2, w0.y, aB[4 * k + 1]);
            aB[4 * k + 2] = fma2(xB2, w1.x, aB[4 * k + 2]);
            aB[4 * k + 3] = fma2(xB2, w1.y, aB[4 * k + 3]);
        }
    }
#pragma unroll
    for (int i = 0; i < 8; i++) {
        const ulonglong2* wr = (const ulonglong2*)&sw[16 + (8 + i) * 16];
        u64 xA2 = pk1(xtA[i]), xB2 = pk1(xtB[i]);
#pragma unroll
        for (int k = 0; k < 2; k++) {
            ulonglong2 w0 = wr[2 * k], w1 = wr[2 * k + 1];
            aA[4 * k + 0] = fma2(xA2, w0.x, aA[4 * k + 0]);
            aA[4 * k + 1] = fma2(xA2, w0.y, aA[4 * k + 1]);
            aA[4 * k + 2] = fma2(xA2, w1.x, aA[4 * k + 2]);
            aA[4 * k + 3] = fma2(xA2, w1.y, aA[4 * k + 3]);
            aB[4 * k + 0] = fma2(xB2, w0.x, aB[4 * k + 0]);
            aB[4 * k + 1] = fma2(xB2, w0.y, aB[4 * k + 1]);
            aB[4 * k + 2] = fma2(xB2, w1.x, aB[4 * k + 2]);
            aB[4 * k + 3] = fma2(xB2, w1.y, aB[4 * k + 3]);
        }
    }
    {
        float efA[4] = {eaA.x, eaA.y, eaA.z, eaA.w};
        float efB[4] = {eaB.x, eaB.y, eaB.z, eaB.w};
#pragma unroll
        for (int i = 0; i < 4; i++) {
            const ulonglong2* wr = (const ulonglong2*)&sw[16 + (16 + i) * 16];
            u64 xA2 = pk1(efA[i]), xB2 = pk1(efB[i]);
#pragma unroll
            for (int k = 0; k < 2; k++) {
                ulonglong2 w0 = wr[2 * k], w1 = wr[2 * k + 1];
                aA[4 * k + 0] = fma2(xA2, w0.x, aA[4 * k + 0]);
                aA[4 * k + 1] = fma2(xA2, w0.y, aA[4 * k + 1]);
                aA[4 * k + 2] = fma2(xA2, w1.x, aA[4 * k + 2]);
                aA[4 * k + 3] = fma2(xA2, w1.y, aA[4 * k + 3]);
                aB[4 * k + 0] = fma2(xB2, w0.x, aB[4 * k + 0]);
                aB[4 * k + 1] = fma2(xB2, w0.y, aB[4 * k + 1]);
                aB[4 * k + 2] = fma2(xB2, w1.x, aB[4 * k + 2]);
                aB[4 * k + 3] = fma2(xB2, w1.y, aB[4 * k + 3]);
            }
        }
    }

    // ---- LN1 stats ----
    float afA[16], afB[16], s1A, k1A, s1B, k1B;
    relu_stats(aA, afA, s1A, k1A);
    relu_stats(aB, afB, s1B, k1B);

    // ---- layer 2 GEMV (weights shared across both edges) ----
    u64 t2A[8], t2B[8];
#pragma unroll
    for (int k = 0; k < 8; k++) { t2A[k] = 0ull; t2B[k] = 0ull; }
#pragma unroll
    for (int i = 0; i < 16; i++) {
        const ulonglong2* wr = (const ulonglong2*)&sw[336 + i * 16];
        u64 xA2 = pk1(afA[i]), xB2 = pk1(afB[i]);
#pragma unroll
        for (int k = 0; k < 2; k++) {
            ulonglong2 w0 = wr[2 * k], w1 = wr[2 * k + 1];
            t2A[4 * k + 0] = fma2(xA2, w0.x, t2A[4 * k + 0]);
            t2A[4 * k + 1] = fma2(xA2, w0.y, t2A[4 * k + 1]);
            t2A[4 * k + 2] = fma2(xA2, w1.x, t2A[4 * k + 2]);
            t2A[4 * k + 3] = fma2(xA2, w1.y, t2A[4 * k + 3]);
            t2B[4 * k + 0] = fma2(xB2, w0.x, t2B[4 * k + 0]);
            t2B[4 * k + 1] = fma2(xB2, w0.y, t2B[4 * k + 1]);
            t2B[4 * k + 2] = fma2(xB2, w1.x, t2B[4 * k + 2]);
            t2B[4 * k + 3] = fma2(xB2, w1.y, t2B[4 * k + 3]);
        }
    }

    // ---- epilogue 2 (per edge) ----
    float bfA[16], bfB[16], s2A, k2A, s2B, k2B;
    epi2(sw, t2A, s1A, k1A, bfA, s2A, k2A);
    epi2(sw, t2B, s1B, k1B, bfB, s2B, k2B);

    // ---- layer 3 (weights shared) ----
    u64 t3aA = 0ull, t3bA = 0ull, t3aB = 0ull, t3bB = 0ull;
#pragma unroll
    for (int i = 0; i < 16; i++) {
        ulonglong2 w = *(const ulonglong2*)&sw[624 + i * 4];
        u64 xA2 = pk1(bfA[i]), xB2 = pk1(bfB[i]);
        t3aA = fma2(xA2, w.x, t3aA);
        t3bA = fma2(xA2, w.y, t3bA);
        t3aB = fma2(xB2, w.x, t3aB);
        t3bB = fma2(xB2, w.y, t3bB);
    }

    u64 cs3a = *(const u64*)&sw[688], cs3b = *(const u64*)&sw[690];
    u64 b3a  = *(const u64*)&sw[692], b3b  = *(const u64*)&sw[694];

    if (vA) {
        u64 nk2 = pk1(-k2A), s2p = pk1(s2A);
        u64 oa = fma2(s2p, t3aA, fma2(nk2, cs3a, b3a));
        u64 ob = fma2(s2p, t3bA, fma2(nk2, cs3b, b3b));
        float2 fa = upk(oa), fb = upk(ob);
        out4[eA] = make_float4(fa.x, fa.y, fb.x, fb.y);
    }
    if (vB) {
        u64 nk2 = pk1(-k2B), s2p = pk1(s2B);
        u64 oa = fma2(s2p, t3aB, fma2(nk2, cs3a, b3a));
        u64 ob = fma2(s2p, t3bB, fma2(nk2, cs3b, b3b));
        float2 fa = upk(oa), fb = upk(ob);
        out4[eB] = make_float4(fa.x, fa.y, fb.x, fb.y);
    }
}

extern "C" void kernel_launch(void* const* d_in, const int* in_sizes, int n_in,
                              void* d_out, int out_size)
{
    const float* x   = (const float*)d_in[0];
    const int*   ei  = (const int*)d_in[1];     // int32 (JAX x64 disabled)
    const float* ea  = (const float*)d_in[2];
    const float* W1  = (const float*)d_in[3];
    const float* b1  = (const float*)d_in[4];
    const float* g1  = (const float*)d_in[5];
    const float* be1 = (const float*)d_in[6];
    const float* W2  = (const float*)d_in[7];
    const float* b2  = (const float*)d_in[8];
    const float* g2  = (const float*)d_in[9];
    const float* be2 = (const float*)d_in[10];
    const float* W3  = (const float*)d_in[11];
    const float* b3  = (const float*)d_in[12];

    int N = in_sizes[0] / 8;
    if (N > MAX_NODES) N = MAX_NODES;
    int E = in_sizes[1] / 2;

    node_kernel<<<(N + 255) / 256, 256>>>((const float4*)x, W1, b1,
                                          g1, be1, W2, b2, g2, be2, W3, b3, N);
    edge_kernel<<<(E + 255) / 256, 128>>>(ei, (const float4*)ea, (float4*)d_out, E);
}

// round 14
// speedup vs baseline: 1.9856x; 1.2150x over previous
#include <cuda_runtime.h>
#include <cuda_fp16.h>

#define MAX_NODES 100000

typedef unsigned long long u64;

// fp16 node features: x[n] as 8 halves = 16B -> ONE gather per endpoint.
__device__ __align__(16) uint4 g_xh[MAX_NODES];

// Folded weights, device-computed staging buffer (copied into c_fold below):
//   [  0.. 15]  b1[16]
//   [ 16..335]  W1[20][16]   (rows 0..7 frm, 8..15 to, 16..19 edge_attr)
//   [336..591]  W2g[16][16] = diag(g1) @ W2
//   [592..607]  cs2[16]     = colsum(W2g)
//   [608..623]  b2f[16]     = b2 + be1 @ W2
//   [624..687]  W3g[16][4]  = diag(g2) @ W3
//   [688..691]  cs3[4]      = colsum(W3g)
//   [692..695]  b3f[4]      = b3 + be2 @ W3
__device__ __align__(16) float g_fold[696];

// Constant-bank copy: weight reads go through the uniform-const port (LDCU),
// NOT through L1tex — frees the L1tex pipe for the random node gathers.
__constant__ __align__(16) float c_fold[696];

// ---- packed f32x2 helpers (sm_103a) ----
__device__ __forceinline__ u64 pk(float lo, float hi) {
    u64 r; asm("mov.b64 %0, {%1, %2};" : "=l"(r) : "f"(lo), "f"(hi)); return r;
}
__device__ __forceinline__ u64 pk1(float v) { return pk(v, v); }
__device__ __forceinline__ float2 upk(u64 v) {
    float2 f; asm("mov.b64 {%0, %1}, %2;" : "=f"(f.x), "=f"(f.y) : "l"(v)); return f;
}
__device__ __forceinline__ u64 fma2(u64 a, u64 b, u64 c) {
    u64 d; asm("fma.rn.f32x2 %0, %1, %2, %3;" : "=l"(d) : "l"(a), "l"(b), "l"(c)); return d;
}
__device__ __forceinline__ u64 add2(u64 a, u64 b) {
    u64 d; asm("add.rn.f32x2 %0, %1, %2;" : "=l"(d) : "l"(a), "l"(b)); return d;
}
// uint4 of 8 halves -> 8 floats
__device__ __forceinline__ void h8f(uint4 h, float* f) {
    float2 t;
    t = __half22float2(*(__half2*)&h.x); f[0] = t.x; f[1] = t.y;
    t = __half22float2(*(__half2*)&h.y); f[2] = t.x; f[3] = t.y;
    t = __half22float2(*(__half2*)&h.z); f[4] = t.x; f[5] = t.y;
    t = __half22float2(*(__half2*)&h.w); f[6] = t.x; f[7] = t.y;
}

// relu + one-pass LN stats on 8 packed accumulators -> 16 floats + (s, s*mu)
__device__ __forceinline__ void relu_stats(const u64* acc, float* af, float& s, float& k) {
    u64 sm = 0ull, ss = 0ull;
#pragma unroll
    for (int i = 0; i < 8; i++) {
        float2 f = upk(acc[i]);
        f.x = fmaxf(f.x, 0.f); f.y = fmaxf(f.y, 0.f);
        af[2 * i] = f.x; af[2 * i + 1] = f.y;
        u64 v = pk(f.x, f.y);
        sm = add2(sm, v);
        ss = fma2(v, v, ss);
    }
    float2 sh = upk(sm), qh = upk(ss);
    float mu  = (sh.x + sh.y) * 0.0625f;
    float var = fmaf(qh.x + qh.y, 0.0625f, -mu * mu);
    s = rsqrtf(var + 1e-5f);
    k = s * mu;
}

// epilogue 2: v = s1*t + (b2f - k1*cs2), relu, stats  (constants from c_fold)
__device__ __forceinline__ void epi2(const u64* t2, float s1, float k1,
                                     float* bf, float& s2, float& k2) {
    u64 nk1 = pk1(-k1), s1p = pk1(s1);
    const u64* csp = (const u64*)&c_fold[592];
    const u64* bfp = (const u64*)&c_fold[608];
    u64 sm = 0ull, ss = 0ull;
#pragma unroll
    for (int i = 0; i < 8; i++) {
        u64 c = fma2(nk1, csp[i], bfp[i]);
        u64 v = fma2(s1p, t2[i], c);
        float2 f = upk(v);
        f.x = fmaxf(f.x, 0.f); f.y = fmaxf(f.y, 0.f);
        bf[2 * i] = f.x; bf[2 * i + 1] = f.y;
        u64 vv = pk(f.x, f.y);
        sm = add2(sm, vv);
        ss = fma2(vv, vv, ss);
    }
    float2 sh = upk(sm), qh = upk(ss);
    float mu  = (sh.x + sh.y) * 0.0625f;
    float var = fmaf(qh.x + qh.y, 0.0625f, -mu * mu);
    s2 = rsqrtf(var + 1e-5f);
    k2 = s2 * mu;
}

__global__ void __launch_bounds__(256)
node_kernel(const float4* __restrict__ x4,
            const float* __restrict__ W1, const float* __restrict__ b1,
            const float* __restrict__ g1, const float* __restrict__ be1,
            const float* __restrict__ W2, const float* __restrict__ b2,
            const float* __restrict__ g2, const float* __restrict__ be2,
            const float* __restrict__ W3, const float* __restrict__ b3,
            int N)
{
    // Block 0 computes the folded-weight block (strided: 320 > blockDim.x).
    if (blockIdx.x == 0) {
        for (int t = threadIdx.x; t < 320; t += blockDim.x) {
            if (t < 16) g_fold[t] = b1[t];
            g_fold[16 + t] = W1[t];                    // full W1 (320)
            if (t < 256) g_fold[336 + t] = g1[t >> 4] * W2[t];
            if (t < 16) {
                float cs = 0.f, bf = b2[t];
                for (int i = 0; i < 16; i++) {
                    cs += g1[i] * W2[i * 16 + t];
                    bf += be1[i] * W2[i * 16 + t];
                }
                g_fold[592 + t] = cs;
                g_fold[608 + t] = bf;
            }
            if (t < 64) g_fold[624 + t] = g2[t >> 2] * W3[t];
            if (t < 4) {
                float cs = 0.f, bf = b3[t];
                for (int i = 0; i < 16; i++) {
                    cs += g2[i] * W3[i * 4 + t];
                    bf += be2[i] * W3[i * 4 + t];
                }
                g_fold[688 + t] = cs;
                g_fold[692 + t] = bf;
            }
        }
    }

    int n = blockIdx.x * blockDim.x + threadIdx.x;
    if (n >= N) return;
    float4 x0 = x4[n * 2 + 0];
    float4 x1 = x4[n * 2 + 1];
    uint4 h;
    __half2 h0 = __floats2half2_rn(x0.x, x0.y);
    __half2 h1 = __floats2half2_rn(x0.z, x0.w);
    __half2 h2 = __floats2half2_rn(x1.x, x1.y);
    __half2 h3 = __floats2half2_rn(x1.z, x1.w);
    h.x = *(unsigned int*)&h0; h.y = *(unsigned int*)&h1;
    h.z = *(unsigned int*)&h2; h.w = *(unsigned int*)&h3;
    g_xh[n] = h;
}

__global__ void __launch_bounds__(128, 6)
edge_kernel(const int* __restrict__ ei, const float4* __restrict__ ea4,
            float4* __restrict__ out4, int E)
{
    int base = blockIdx.x * 256 + threadIdx.x;
    int eA = base, eB = base + 128;
    bool vA = eA < E, vB = eB < E;
    int sA = vA ? eA : 0, sB = vB ? eB : 0;

    // ---- issue all irregular loads up front (max MLP) ----
    int fA = ei[sA],     fB = ei[sB];
    int tA = ei[E + sA], tB = ei[E + sB];
    uint4 hfA = g_xh[fA], htA = g_xh[tA];
    uint4 hfB = g_xh[fB], htB = g_xh[tB];
    float4 eaA = ea4[sA], eaB = ea4[sB];

    float xfA[8], xtA[8], xfB[8], xtB[8];
    h8f(hfA, xfA); h8f(htA, xtA);
    h8f(hfB, xfB); h8f(htB, xtB);

    // ---- layer 1: acc = b1 + xf@W1[0:8] + xt@W1[8:16] + ea@W1[16:20] ----
    u64 aA[8], aB[8];
    {
        const u64* b1p = (const u64*)&c_fold[0];
#pragma unroll
        for (int k = 0; k < 8; k++) { aA[k] = b1p[k]; aB[k] = aA[k]; }
    }
#pragma unroll
    for (int i = 0; i < 8; i++) {
        const ulonglong2* wr = (const ulonglong2*)&c_fold[16 + i * 16];
        u64 xA2 = pk1(xfA[i]), xB2 = pk1(xfB[i]);
#pragma unroll
        for (int k = 0; k < 2; k++) {
            ulonglong2 w0 = wr[2 * k], w1 = wr[2 * k + 1];
            aA[4 * k + 0] = fma2(xA2, w0.x, aA[4 * k + 0]);
            aA[4 * k + 1] = fma2(xA2, w0.y, aA[4 * k + 1]);
            aA[4 * k + 2] = fma2(xA2, w1.x, aA[4 * k + 2]);
            aA[4 * k + 3] = fma2(xA2, w1.y, aA[4 * k + 3]);
            aB[4 * k + 0] = fma2(xB2, w0.x, aB[4 * k + 0]);
            aB[4 * k + 1] = fma2(xB2, w0.y, aB[4 * k + 1]);
            aB[4 * k + 2] = fma2(xB2, w1.x, aB[4 * k + 2]);
            aB[4 * k + 3] = fma2(xB2, w1.y, aB[4 * k + 3]);
        }
    }
#pragma unroll
    for (int i = 0; i < 8; i++) {
        const ulonglong2* wr = (const ulonglong2*)&c_fold[16 + (8 + i) * 16];
        u64 xA2 = pk1(xtA[i]), xB2 = pk1(xtB[i]);
#pragma unroll
        for (int k = 0; k < 2; k++) {
            ulonglong2 w0 = wr[2 * k], w1 = wr[2 * k + 1];
            aA[4 * k + 0] = fma2(xA2, w0.x, aA[4 * k + 0]);
            aA[4 * k + 1] = fma2(xA2, w0.y, aA[4 * k + 1]);
            aA[4 * k + 2] = fma2(xA2, w1.x, aA[4 * k + 2]);
            aA[4 * k + 3] = fma2(xA2, w1.y, aA[4 * k + 3]);
            aB[4 * k + 0] = fma2(xB2, w0.x, aB[4 * k + 0]);
            aB[4 * k + 1] = fma2(xB2, w0.y, aB[4 * k + 1]);
            aB[4 * k + 2] = fma2(xB2, w1.x, aB[4 * k + 2]);
            aB[4 * k + 3] = fma2(xB2, w1.y, aB[4 * k + 3]);
        }
    }
    {
        float efA[4] = {eaA.x, eaA.y, eaA.z, eaA.w};
        float efB[4] = {eaB.x, eaB.y, eaB.z, eaB.w};
#pragma unroll
        for (int i = 0; i < 4; i++) {
            const ulonglong2* wr = (const ulonglong2*)&c_fold[16 + (16 + i) * 16];
            u64 xA2 = pk1(efA[i]), xB2 = pk1(efB[i]);
#pragma unroll
            for (int k = 0; k < 2; k++) {
                ulonglong2 w0 = wr[2 * k], w1 = wr[2 * k + 1];
                aA[4 * k + 0] = fma2(xA2, w0.x, aA[4 * k + 0]);
                aA[4 * k + 1] = fma2(xA2, w0.y, aA[4 * k + 1]);
                aA[4 * k + 2] = fma2(xA2, w1.x, aA[4 * k + 2]);
                aA[4 * k + 3] = fma2(xA2, w1.y, aA[4 * k + 3]);
                aB[4 * k + 0] = fma2(xB2, w0.x, aB[4 * k + 0]);
                aB[4 * k + 1] = fma2(xB2, w0.y, aB[4 * k + 1]);
                aB[4 * k + 2] = fma2(xB2, w1.x, aB[4 * k + 2]);
                aB[4 * k + 3] = fma2(xB2, w1.y, aB[4 * k + 3]);
            }
        }
    }

    // ---- LN1 stats ----
    float afA[16], afB[16], s1A, k1A, s1B, k1B;
    relu_stats(aA, afA, s1A, k1A);
    relu_stats(aB, afB, s1B, k1B);

    // ---- layer 2 GEMV (weights from constant bank) ----
    u64 t2A[8], t2B[8];
#pragma unroll
    for (int k = 0; k < 8; k++) { t2A[k] = 0ull; t2B[k] = 0ull; }
#pragma unroll
    for (int i = 0; i < 16; i++) {
        const ulonglong2* wr = (const ulonglong2*)&c_fold[336 + i * 16];
        u64 xA2 = pk1(afA[i]), xB2 = pk1(afB[i]);
#pragma unroll
        for (int k = 0; k < 2; k++) {
            ulonglong2 w0 = wr[2 * k], w1 = wr[2 * k + 1];
            t2A[4 * k + 0] = fma2(xA2, w0.x, t2A[4 * k + 0]);
            t2A[4 * k + 1] = fma2(xA2, w0.y, t2A[4 * k + 1]);
            t2A[4 * k + 2] = fma2(xA2, w1.x, t2A[4 * k + 2]);
            t2A[4 * k + 3] = fma2(xA2, w1.y, t2A[4 * k + 3]);
            t2B[4 * k + 0] = fma2(xB2, w0.x, t2B[4 * k + 0]);
            t2B[4 * k + 1] = fma2(xB2, w0.y, t2B[4 * k + 1]);
            t2B[4 * k + 2] = fma2(xB2, w1.x, t2B[4 * k + 2]);
            t2B[4 * k + 3] = fma2(xB2, w1.y, t2B[4 * k + 3]);
        }
    }

    // ---- epilogue 2 (per edge) ----
    float bfA[16], bfB[16], s2A, k2A, s2B, k2B;
    epi2(t2A, s1A, k1A, bfA, s2A, k2A);
    epi2(t2B, s1B, k1B, bfB, s2B, k2B);

    // ---- layer 3 (weights from constant bank) ----
    u64 t3aA = 0ull, t3bA = 0ull, t3aB = 0ull, t3bB = 0ull;
#pragma unroll
    for (int i = 0; i < 16; i++) {
        ulonglong2 w = *(const ulonglong2*)&c_fold[624 + i * 4];
        u64 xA2 = pk1(bfA[i]), xB2 = pk1(bfB[i]);
        t3aA = fma2(xA2, w.x, t3aA);
        t3bA = fma2(xA2, w.y, t3bA);
        t3aB = fma2(xB2, w.x, t3aB);
        t3bB = fma2(xB2, w.y, t3bB);
    }

    u64 cs3a = *(const u64*)&c_fold[688], cs3b = *(const u64*)&c_fold[690];
    u64 b3a  = *(const u64*)&c_fold[692], b3b  = *(const u64*)&c_fold[694];

    if (vA) {
        u64 nk2 = pk1(-k2A), s2p = pk1(s2A);
        u64 oa = fma2(s2p, t3aA, fma2(nk2, cs3a, b3a));
        u64 ob = fma2(s2p, t3bA, fma2(nk2, cs3b, b3b));
        float2 fa = upk(oa), fb = upk(ob);
        out4[eA] = make_float4(fa.x, fa.y, fb.x, fb.y);
    }
    if (vB) {
        u64 nk2 = pk1(-k2B), s2p = pk1(s2B);
        u64 oa = fma2(s2p, t3aB, fma2(nk2, cs3a, b3a));
        u64 ob = fma2(s2p, t3bB, fma2(nk2, cs3b, b3b));
        float2 fa = upk(oa), fb = upk(ob);
        out4[eB] = make_float4(fa.x, fa.y, fb.x, fb.y);
    }
}

extern "C" void kernel_launch(void* const* d_in, const int* in_sizes, int n_in,
                              void* d_out, int out_size)
{
    const float* x   = (const float*)d_in[0];
    const int*   ei  = (const int*)d_in[1];     // int32 (JAX x64 disabled)
    const float* ea  = (const float*)d_in[2];
    const float* W1  = (const float*)d_in[3];
    const float* b1  = (const float*)d_in[4];
    const float* g1  = (const float*)d_in[5];
    const float* be1 = (const float*)d_in[6];
    const float* W2  = (const float*)d_in[7];
    const float* b2  = (const float*)d_in[8];
    const float* g2  = (const float*)d_in[9];
    const float* be2 = (const float*)d_in[10];
    const float* W3  = (const float*)d_in[11];
    const float* b3  = (const float*)d_in[12];

    int N = in_sizes[0] / 8;
    if (N > MAX_NODES) N = MAX_NODES;
    int E = in_sizes[1] / 2;

    node_kernel<<<(N + 255) / 256, 256>>>((const float4*)x, W1, b1,
                                          g1, be1, W2, b2, g2, be2, W3, b3, N);

    // Stage folded weights into the constant bank (D2D async: graph-capturable).
    void* gfold_dev = nullptr;
    cudaGetSymbolAddress(&gfold_dev, g_fold);
    cudaMemcpyToSymbolAsync(c_fold, gfold_dev, 696 * sizeof(float), 0,
                            cudaMemcpyDeviceToDevice, 0);

    edge_kernel<<<(E + 255) / 256, 128>>>(ei, (const float4*)ea, (float4*)d_out, E);
}